// round 15
// baseline (speedup 1.0000x reference)
#include <cuda_runtime.h>

// EnergyGatedDeltaModel — GB300 sm_103a
// R14 = R11/R13 arithmetic (bit-identical decisions) with FOUR batches per
// warp (128 CTAs; the scan is latency-bound — R13 proved instruction count
// is not binding — so 4 independent dependency chains hide each other's
// dot/div/butterfly latency). Static pairs (0,1) and (2,3) each reuse the
// proven paired slow-path; two parity-matched mo buffers serve rebuilds.

#define B_ 512
#define L_ 2048
#define H_ 32
#define V_ 64
#define STEPS (L_ - 1)
#define THRESH 1.0f
#define ROWP 36
// bank-stagger layout: consecutive deltas 1168 words ≡ 16 (mod 32 banks)
#define OFF_MN0 0
#define OFF_MN1 1168
#define OFF_MN2 2352
#define OFF_MN3 3520
#define OFF_MOA 4688   // ≡16 mod 32  -> rebuild partner for mn≡0 (batches 0,3)
#define OFF_MOB 5856   // ≡0  mod 32  -> rebuild partner for mn≡16 (batches 1,2)
#define SLOWBUF_WORDS (OFF_MOB + H_ * ROWP)

typedef unsigned long long u64;

__device__ float g_table[V_ * H_];
__device__ float g_ksq[V_];
__device__ float g_denom[V_];
__device__ int   g_writes;

// ---- packed f32x2 primitives (two independent IEEE fp32 ops per instr) ----
__device__ __forceinline__ u64 pk2(float lo, float hi) {
    u64 r; asm("mov.b64 %0, {%1,%2};" : "=l"(r) : "f"(lo), "f"(hi)); return r;
}
__device__ __forceinline__ void upk2(float& lo, float& hi, u64 v) {
    asm("mov.b64 {%0,%1}, %2;" : "=f"(lo), "=f"(hi) : "l"(v));
}
__device__ __forceinline__ u64 mul2_(u64 a, u64 b) {
    u64 r; asm("mul.rn.f32x2 %0, %1, %2;" : "=l"(r) : "l"(a), "l"(b)); return r;
}
__device__ __forceinline__ u64 add2_(u64 a, u64 b) {
    u64 r; asm("add.rn.f32x2 %0, %1, %2;" : "=l"(r) : "l"(a), "l"(b)); return r;
}
__device__ __forceinline__ u64 fma2_(u64 a, u64 b, u64 c) {
    u64 r; asm("fma.rn.f32x2 %0, %1, %2, %3;" : "=l"(r) : "l"(a), "l"(b), "l"(c)); return r;
}

// Packed butterfly over 32 lanes (order-insensitive: fast-gate dE only).
__device__ __forceinline__ u64 bfly_sum2(u64 v, unsigned FULL) {
    float lo, hi;
    upk2(lo, hi, v);
#pragma unroll
    for (int o = 16; o > 0; o >>= 1) {
        float slo = __shfl_xor_sync(FULL, lo, o);
        float shi = __shfl_xor_sync(FULL, hi, o);
        u64 acc = add2_(pk2(lo, hi), pk2(slo, shi));
        upk2(lo, hi, acc);
    }
    return pk2(lo, hi);
}

// Packed NEON VF4xIC4 dot (per-element order identical to scalar neon_dot32).
__device__ __forceinline__ float dot2p(const u64* x2, const float* k) {
    const u64* y2 = (const u64*)k;
    u64 A2[8];
#pragma unroll
    for (int c = 0; c < 8; c++) A2[c] = mul2_(x2[c], y2[c]);
#pragma unroll
    for (int c = 0; c < 8; c++) A2[c] = fma2_(x2[8 + c], y2[8 + c], A2[c]);
    u64 W01 = add2_(add2_(add2_(A2[0], A2[2]), A2[4]), A2[6]);
    u64 W23 = add2_(add2_(add2_(A2[1], A2[3]), A2[5]), A2[7]);
    u64 R = add2_(W01, W23);
    float rl, rh; upk2(rl, rh, R);
    return __fadd_rn(rl, rh);
}

__device__ __forceinline__ float neon_sum32(const float* t) {
    float A[16];
#pragma unroll
    for (int c = 0; c < 16; c++) A[c] = __fadd_rn(t[c], t[16 + c]);
    float V[4];
#pragma unroll
    for (int l = 0; l < 4; l++)
        V[l] = __fadd_rn(__fadd_rn(__fadd_rn(A[l], A[4 + l]), A[8 + l]), A[12 + l]);
    return __fadd_rn(__fadd_rn(V[0], V[2]), __fadd_rn(V[1], V[3]));
}

// ---------------------------------------------------------------------------
__global__ void precompute_kernel(const float* __restrict__ embed,
                                  const float* __restrict__ w1,
                                  const float* __restrict__ b1,
                                  const float* __restrict__ w2,
                                  const float* __restrict__ b2,
                                  const float* __restrict__ ln_g,
                                  const float* __restrict__ ln_b)
{
    __shared__ float h_sh[H_];
    __shared__ float s_sh[2 * H_];
    __shared__ float x_sh[H_];

    const int v = blockIdx.x;
    const int t = threadIdx.x;
    if (v == 0 && t == 0) g_writes = 0;

    if (t < H_) h_sh[t] = embed[v * H_ + t];
    __syncthreads();

    {
        const int j = t;
        float s = 0.0f;
#pragma unroll
        for (int i = 0; i < H_; i++) s = fmaf(h_sh[i], w1[i * 2 * H_ + j], s);
        s = __fadd_rn(s, b1[j]);
        s_sh[j] = fmaxf(s, 0.0f);
    }
    __syncthreads();

    if (t < H_) {
        const int i = t;
        float acc = 0.0f;
#pragma unroll
        for (int j = 0; j < 2 * H_; j++) acc = fmaf(s_sh[j], w2[j * H_ + i], acc);
        float ff = __fadd_rn(acc, b2[i]);
        x_sh[i] = __fadd_rn(h_sh[i], ff);
    }
    __syncthreads();

    if (t == 0) {
        float x[H_], d[H_], sq[H_];
#pragma unroll
        for (int i = 0; i < H_; i++) x[i] = x_sh[i];
        float mu = __fmul_rn(neon_sum32(x), 1.0f / H_);
#pragma unroll
        for (int i = 0; i < H_; i++) {
            d[i] = __fsub_rn(x[i], mu);
            sq[i] = __fmul_rn(d[i], d[i]);
        }
        float var = __fmul_rn(neon_sum32(sq), 1.0f / H_);
        float rs = __fdiv_rn(1.0f, __fsqrt_rn(__fadd_rn(var, 1e-5f)));
        float y[H_];
#pragma unroll
        for (int i = 0; i < H_; i++) {
            y[i] = __fadd_rn(__fmul_rn(__fmul_rn(d[i], rs), ln_g[i]), ln_b[i]);
            g_table[v * H_ + i] = y[i];
            sq[i] = __fmul_rn(y[i], y[i]);
        }
        float ksq = neon_sum32(sq);
        g_ksq[v]   = ksq;
        g_denom[v] = __fadd_rn(ksq, 1e-6f);
    }
}

// ---------------------------------------------------------------------------
// Slow-path primitives (values identical to R11).
// ---------------------------------------------------------------------------
__device__ __forceinline__ float chain64p(const float* P, int c) {
    float a = 0.0f;
#pragma unroll
    for (int g = 0; g < 4; g++) {
        float s[16];
#pragma unroll
        for (int i = 0; i < 16; i++) {
            const int m = g * 16 + i;
            s[i] = P[(m >> 1) * ROWP + (m & 1) * 16 + c];
        }
#pragma unroll
        for (int i = 0; i < 16; i++)
            a = fmaf(s[i], s[i], a);
    }
    return a;
}

__device__ __forceinline__ float fold16(float val, int base, unsigned FULL) {
    float V[4];
#pragma unroll
    for (int l = 0; l < 4; l++) {
        float a0 = __shfl_sync(FULL, val, base + l);
        float a1 = __shfl_sync(FULL, val, base + l + 4);
        float a2 = __shfl_sync(FULL, val, base + l + 8);
        float a3 = __shfl_sync(FULL, val, base + l + 12);
        V[l] = __fadd_rn(__fadd_rn(__fadd_rn(a0, a1), a2), a3);
    }
    return __fadd_rn(__fadd_rn(V[0], V[2]), __fadd_rn(V[1], V[3]));
}

__device__ __forceinline__ void store_row2(float* buf, int lane, const u64* M2) {
    ulonglong2* p = (ulonglong2*)(buf + lane * ROWP);
#pragma unroll
    for (int q = 0; q < 8; q++) {
        ulonglong2 v;
        v.x = M2[2 * q];
        v.y = M2[2 * q + 1];
        p[q] = v;
    }
}

__device__ __forceinline__ void store_row_mn2(float* buf, int lane, const u64* M2,
                                              u64 u2, const float* k) {
    const u64* k2 = (const u64*)k;
    ulonglong2* p = (ulonglong2*)(buf + lane * ROWP);
#pragma unroll
    for (int q = 0; q < 8; q++) {
        ulonglong2 v;
        v.x = fma2_(u2, k2[2 * q],     M2[2 * q]);
        v.y = fma2_(u2, k2[2 * q + 1], M2[2 * q + 1]);
        p[q] = v;
    }
}

__device__ __forceinline__ int resolve_single(const u64* M2, u64 u2, const float* k,
                                              float& eo, bool& valid,
                                              float* mnbuf, float* mobuf,
                                              int lane, unsigned FULL)
{
    int g;
    if (valid) {
        store_row_mn2(mnbuf, lane, M2, u2, k);
        __syncwarp();
        float a = 0.0f;
        if (lane < 16) a = chain64p(mnbuf, lane);
        __syncwarp();
        float en = fold16(a, 0, FULL);
        g = en > eo;
        if (g) eo = en;
    } else {
        store_row2(mobuf, lane, M2);
        store_row_mn2(mnbuf, lane, M2, u2, k);
        __syncwarp();
        float a = chain64p((lane < 16) ? mobuf : mnbuf, lane & 15);
        __syncwarp();
        float eoc = fold16(a, 0, FULL);
        float en  = fold16(a, 16, FULL);
        g = en > eoc;
        eo = g ? en : eoc;
        valid = true;
    }
    return g;
}

// Full slow resolution for a static pair (X, Y).
__device__ __forceinline__ void slow_resolve_pair(
    int& gateX, int& gateY, bool slowX, bool slowY,
    const u64* M2X, u64 u2X, const float* kX,
    const u64* M2Y, u64 u2Y, const float* kY,
    float& eoX, float& eoY, bool& validX, bool& validY,
    float* mnX, float* mnY, float* moX, float* moY,
    int lane, unsigned FULL)
{
    if (slowX & slowY & validX & validY) {
        store_row_mn2(mnX, lane, M2X, u2X, kX);
        store_row_mn2(mnY, lane, M2Y, u2Y, kY);
        __syncwarp();
        float a = chain64p((lane < 16) ? mnX : mnY, lane & 15);
        __syncwarp();
        float enX = fold16(a, 0, FULL);
        float enY = fold16(a, 16, FULL);
        gateX = enX > eoX;
        gateY = enY > eoY;
        if (gateX) eoX = enX;
        if (gateY) eoY = enY;
    } else {
        if (slowX)
            gateX = resolve_single(M2X, u2X, kX, eoX, validX, mnX, moX, lane, FULL);
        if (slowY)
            gateY = resolve_single(M2Y, u2Y, kY, eoY, validY, mnY, moY, lane, FULL);
    }
}

// ---------------------------------------------------------------------------
__global__ void __launch_bounds__(32, 1) scan_kernel(const int* __restrict__ seq,
                                                     const float* __restrict__ w_read,
                                                     const float* __restrict__ b_read,
                                                     const float* __restrict__ w_out,
                                                     const float* __restrict__ b_out,
                                                     float* __restrict__ out)
{
    __shared__ __align__(16) float tsh[V_ * H_];
    __shared__ __align__(16) float slowbuf[SLOWBUF_WORDS];
    __shared__ float dnsh[V_];
    __shared__ float kssh[V_];
    __shared__ int   toks[4][32];
    __shared__ float scratch[H_];

    const int lane = threadIdx.x;
    const unsigned FULL = 0xffffffffu;
    float* mn[4] = { slowbuf + OFF_MN0, slowbuf + OFF_MN1,
                     slowbuf + OFF_MN2, slowbuf + OFF_MN3 };
    // rebuild partner parity: mn0≡0 & mn3≡0 -> moA(≡16); mn1≡16 & mn2≡16 -> moB(≡0)
    float* mo[4] = { slowbuf + OFF_MOA, slowbuf + OFF_MOB,
                     slowbuf + OFF_MOB, slowbuf + OFF_MOA };

    for (int i = lane; i < V_ * H_; i += 32) tsh[i] = g_table[i];
    dnsh[lane]      = g_denom[lane];
    dnsh[lane + 32] = g_denom[lane + 32];
    kssh[lane]      = g_ksq[lane];
    kssh[lane + 32] = g_ksq[lane + 32];
    __syncwarp();

    u64 M2[4][16];
#pragma unroll
    for (int p = 0; p < 4; p++)
#pragma unroll
        for (int j = 0; j < 16; j++) M2[p][j] = 0ULL;

    float eo[4] = {0.0f, 0.0f, 0.0f, 0.0f};
    bool valid[4] = {true, true, true, true};

    int writes = 0;
    const int* sb[4];
#pragma unroll
    for (int p = 0; p < 4; p++) sb[p] = seq + (blockIdx.x + p * 128) * L_;

    for (int t0 = 0; t0 < STEPS; t0 += 32) {
#pragma unroll
        for (int p = 0; p < 4; p++) toks[p][lane] = sb[p][t0 + lane];
        __syncwarp();
        const int tend = (STEPS - t0) < 32 ? (STEPS - t0) : 32;

        for (int tt = 0; tt < tend; tt++) {
            const float* k[4];
            float dn[4], ks[4];
#pragma unroll
            for (int p = 0; p < 4; p++) {
                const int tok = toks[p][tt];
                k[p]  = tsh + tok * H_;
                dn[p] = dnsh[tok];
                ks[p] = kssh[tok];
            }

            // 4 independent packed NEON dots (interleaved by scheduler)
            float v[4];
#pragma unroll
            for (int p = 0; p < 4; p++) v[p] = dot2p(M2[p], k[p]);

            float u[4];
#pragma unroll
            for (int p = 0; p < 4; p++)
                u[p] = __fsub_rn(k[p][lane], __fdiv_rn(v[p], dn[p]));

            // 4 packed butterflies (interleaved)
            u64 r[4];
#pragma unroll
            for (int p = 0; p < 4; p++)
                r[p] = bfly_sum2(pk2(__fmul_rn(u[p], v[p]), __fmul_rn(u[p], u[p])), FULL);

            float dE[4];
            bool slow[4];
            int gate[4];
            u64 u2[4];
#pragma unroll
            for (int p = 0; p < 4; p++) {
                float suv, suu;
                upk2(suv, suu, r[p]);
                dE[p] = __fadd_rn(__fadd_rn(suv, suv), __fmul_rn(suu, ks[p]));
                slow[p] = fabsf(dE[p]) < THRESH;
                gate[p] = dE[p] > 0.0f;
                u2[p] = pk2(u[p], u[p]);
            }

            if (slow[0] | slow[1])
                slow_resolve_pair(gate[0], gate[1], slow[0], slow[1],
                                  M2[0], u2[0], k[0], M2[1], u2[1], k[1],
                                  eo[0], eo[1], valid[0], valid[1],
                                  mn[0], mn[1], mo[0], mo[1], lane, FULL);
            if (slow[2] | slow[3])
                slow_resolve_pair(gate[2], gate[3], slow[2], slow[3],
                                  M2[2], u2[2], k[2], M2[3], u2[3], k[3],
                                  eo[2], eo[3], valid[2], valid[3],
                                  mn[2], mn[3], mo[2], mo[3], lane, FULL);

#pragma unroll
            for (int p = 0; p < 4; p++) {
                if (gate[p]) {
                    writes++;
                    const u64* k2 = (const u64*)k[p];
#pragma unroll
                    for (int j = 0; j < 16; j++) M2[p][j] = fma2_(u2[p], k2[j], M2[p][j]);
                    if (!slow[p]) valid[p] = false;
                }
            }
        }
        __syncwarp();
    }

    // -------- readout (4 batches), identical arithmetic --------
#pragma unroll
    for (int pass = 0; pass < 4; pass++) {
        const int b = blockIdx.x + pass * 128;
        const int qtok = sb[pass][L_ - 1];
        const float* qv = tsh + qtok * H_;
        float ctx = dot2p(M2[pass], qv);

        scratch[lane] = ctx;
        __syncwarp();
        float rr = 0.0f;
#pragma unroll
        for (int j = 0; j < H_; j++) rr = fmaf(scratch[j], w_read[j * H_ + lane], rr);
        rr = __fadd_rn(rr, b_read[lane]);
        __syncwarp();
        scratch[lane] = rr;
        __syncwarp();

        float o0 = 0.0f, o1 = 0.0f;
#pragma unroll
        for (int j = 0; j < H_; j++) {
            const float rj = scratch[j];
            o0 = fmaf(rj, w_out[j * V_ + lane], o0);
            o1 = fmaf(rj, w_out[j * V_ + lane + H_], o1);
        }
        out[b * V_ + lane]      = __fadd_rn(o0, b_out[lane]);
        out[b * V_ + lane + H_] = __fadd_rn(o1, b_out[lane + H_]);
        __syncwarp();
    }

    if (lane == 0) atomicAdd(&g_writes, writes);
}

// ---------------------------------------------------------------------------
__global__ void finalize_kernel(float* __restrict__ out, int out_size)
{
    if (out_size > B_ * V_)
        out[B_ * V_] = __fdiv_rn((float)g_writes, (float)(STEPS * B_));
}

extern "C" void kernel_launch(void* const* d_in, const int* in_sizes, int n_in,
                              void* d_out, int out_size)
{
    const int*   seq    = (const int*)d_in[0];
    const float* embed  = (const float*)d_in[1];
    const float* w1     = (const float*)d_in[2];
    const float* b1     = (const float*)d_in[3];
    const float* w2     = (const float*)d_in[4];
    const float* b2     = (const float*)d_in[5];
    const float* ln_g   = (const float*)d_in[6];
    const float* ln_b   = (const float*)d_in[7];
    const float* w_read = (const float*)d_in[8];
    const float* b_read = (const float*)d_in[9];
    const float* w_out  = (const float*)d_in[10];
    const float* b_out  = (const float*)d_in[11];
    float* out = (float*)d_out;

    precompute_kernel<<<V_, 64>>>(embed, w1, b1, w2, b2, ln_g, ln_b);
    scan_kernel<<<B_ / 4, 32>>>(seq, w_read, b_read, w_out, b_out, out);
    finalize_kernel<<<1, 1>>>(out, out_size);
}

// round 16
// speedup vs baseline: 2.1667x; 2.1667x over previous
#include <cuda_runtime.h>

// EnergyGatedDeltaModel — GB300 sm_103a
// R15 = R13 (2-batch/warp, packed f32x2, paired exact slow path — decisions
// bit-identical to R11/R8) with the fast-gate butterflies replaced by
// fixed-point s32 redux (__reduce_add_sync, sm_80+):
//   dE approx error <= 0.14 (scale 4096, rigorous overflow bound via
//   Cauchy-Schwarz: sum|u_i v_i| <= 3.6e4 -> 1.5e8 < 2^31), certification
//   margin THRESH(1.0) - 0.14 >= reference-noise 0.3 -> decisions unchanged.

#define B_ 512
#define L_ 2048
#define H_ 32
#define V_ 64
#define STEPS (L_ - 1)
#define THRESH 1.0f
#define FIXSCALE 4096.0f
#define ROWP 36
#define OFF_MNA 0
#define OFF_MNB 1168
#define OFF_MOA 2352
#define OFF_MOB 3520
#define SLOWBUF_WORDS (OFF_MOB + H_ * ROWP)

typedef unsigned long long u64;

__device__ float g_table[V_ * H_];
__device__ float g_ksq[V_];
__device__ float g_denom[V_];
__device__ int   g_writes;

// ---- packed f32x2 primitives ----
__device__ __forceinline__ u64 pk2(float lo, float hi) {
    u64 r; asm("mov.b64 %0, {%1,%2};" : "=l"(r) : "f"(lo), "f"(hi)); return r;
}
__device__ __forceinline__ void upk2(float& lo, float& hi, u64 v) {
    asm("mov.b64 {%0,%1}, %2;" : "=f"(lo), "=f"(hi) : "l"(v));
}
__device__ __forceinline__ u64 mul2_(u64 a, u64 b) {
    u64 r; asm("mul.rn.f32x2 %0, %1, %2;" : "=l"(r) : "l"(a), "l"(b)); return r;
}
__device__ __forceinline__ u64 add2_(u64 a, u64 b) {
    u64 r; asm("add.rn.f32x2 %0, %1, %2;" : "=l"(r) : "l"(a), "l"(b)); return r;
}
__device__ __forceinline__ u64 fma2_(u64 a, u64 b, u64 c) {
    u64 r; asm("fma.rn.f32x2 %0, %1, %2, %3;" : "=l"(r) : "l"(a), "l"(b), "l"(c)); return r;
}

// Fixed-point redux fast-gate dE (order-insensitive classification only).
__device__ __forceinline__ float dE_fast(float u, float v, float ks, unsigned FULL) {
    const int i1 = __float2int_rn(__fmul_rn(u, v) * FIXSCALE);
    const int i2 = __float2int_rn(__fmul_rn(u, u) * FIXSCALE);
    const int s1 = __reduce_add_sync(FULL, i1);
    const int s2 = __reduce_add_sync(FULL, i2);
    const float suv = __int2float_rn(s1) * (1.0f / FIXSCALE);
    const float suu = __int2float_rn(s2) * (1.0f / FIXSCALE);
    return __fadd_rn(__fadd_rn(suv, suv), __fmul_rn(suu, ks));
}

// Packed NEON VF4xIC4 dot (per-element order identical to scalar neon_dot32).
__device__ __forceinline__ float dot2p(const u64* x2, const float* k) {
    const u64* y2 = (const u64*)k;
    u64 A2[8];
#pragma unroll
    for (int c = 0; c < 8; c++) A2[c] = mul2_(x2[c], y2[c]);
#pragma unroll
    for (int c = 0; c < 8; c++) A2[c] = fma2_(x2[8 + c], y2[8 + c], A2[c]);
    u64 W01 = add2_(add2_(add2_(A2[0], A2[2]), A2[4]), A2[6]);
    u64 W23 = add2_(add2_(add2_(A2[1], A2[3]), A2[5]), A2[7]);
    u64 R = add2_(W01, W23);
    float rl, rh; upk2(rl, rh, R);
    return __fadd_rn(rl, rh);
}

__device__ __forceinline__ float neon_sum32(const float* t) {
    float A[16];
#pragma unroll
    for (int c = 0; c < 16; c++) A[c] = __fadd_rn(t[c], t[16 + c]);
    float V[4];
#pragma unroll
    for (int l = 0; l < 4; l++)
        V[l] = __fadd_rn(__fadd_rn(__fadd_rn(A[l], A[4 + l]), A[8 + l]), A[12 + l]);
    return __fadd_rn(__fadd_rn(V[0], V[2]), __fadd_rn(V[1], V[3]));
}

// ---------------------------------------------------------------------------
__global__ void precompute_kernel(const float* __restrict__ embed,
                                  const float* __restrict__ w1,
                                  const float* __restrict__ b1,
                                  const float* __restrict__ w2,
                                  const float* __restrict__ b2,
                                  const float* __restrict__ ln_g,
                                  const float* __restrict__ ln_b)
{
    __shared__ float h_sh[H_];
    __shared__ float s_sh[2 * H_];
    __shared__ float x_sh[H_];

    const int v = blockIdx.x;
    const int t = threadIdx.x;
    if (v == 0 && t == 0) g_writes = 0;

    if (t < H_) h_sh[t] = embed[v * H_ + t];
    __syncthreads();

    {
        const int j = t;
        float s = 0.0f;
#pragma unroll
        for (int i = 0; i < H_; i++) s = fmaf(h_sh[i], w1[i * 2 * H_ + j], s);
        s = __fadd_rn(s, b1[j]);
        s_sh[j] = fmaxf(s, 0.0f);
    }
    __syncthreads();

    if (t < H_) {
        const int i = t;
        float acc = 0.0f;
#pragma unroll
        for (int j = 0; j < 2 * H_; j++) acc = fmaf(s_sh[j], w2[j * H_ + i], acc);
        float ff = __fadd_rn(acc, b2[i]);
        x_sh[i] = __fadd_rn(h_sh[i], ff);
    }
    __syncthreads();

    if (t == 0) {
        float x[H_], d[H_], sq[H_];
#pragma unroll
        for (int i = 0; i < H_; i++) x[i] = x_sh[i];
        float mu = __fmul_rn(neon_sum32(x), 1.0f / H_);
#pragma unroll
        for (int i = 0; i < H_; i++) {
            d[i] = __fsub_rn(x[i], mu);
            sq[i] = __fmul_rn(d[i], d[i]);
        }
        float var = __fmul_rn(neon_sum32(sq), 1.0f / H_);
        float rs = __fdiv_rn(1.0f, __fsqrt_rn(__fadd_rn(var, 1e-5f)));
        float y[H_];
#pragma unroll
        for (int i = 0; i < H_; i++) {
            y[i] = __fadd_rn(__fmul_rn(__fmul_rn(d[i], rs), ln_g[i]), ln_b[i]);
            g_table[v * H_ + i] = y[i];
            sq[i] = __fmul_rn(y[i], y[i]);
        }
        float ksq = neon_sum32(sq);
        g_ksq[v]   = ksq;
        g_denom[v] = __fadd_rn(ksq, 1e-6f);
    }
}

// ---------------------------------------------------------------------------
// Slow-path primitives (values identical to R11).
// ---------------------------------------------------------------------------
__device__ __forceinline__ float chain64p(const float* P, int c) {
    float a = 0.0f;
#pragma unroll
    for (int g = 0; g < 4; g++) {
        float s[16];
#pragma unroll
        for (int i = 0; i < 16; i++) {
            const int m = g * 16 + i;
            s[i] = P[(m >> 1) * ROWP + (m & 1) * 16 + c];
        }
#pragma unroll
        for (int i = 0; i < 16; i++)
            a = fmaf(s[i], s[i], a);
    }
    return a;
}

__device__ __forceinline__ float fold16(float val, int base, unsigned FULL) {
    float V[4];
#pragma unroll
    for (int l = 0; l < 4; l++) {
        float a0 = __shfl_sync(FULL, val, base + l);
        float a1 = __shfl_sync(FULL, val, base + l + 4);
        float a2 = __shfl_sync(FULL, val, base + l + 8);
        float a3 = __shfl_sync(FULL, val, base + l + 12);
        V[l] = __fadd_rn(__fadd_rn(__fadd_rn(a0, a1), a2), a3);
    }
    return __fadd_rn(__fadd_rn(V[0], V[2]), __fadd_rn(V[1], V[3]));
}

__device__ __forceinline__ void store_row2(float* buf, int lane, const u64* M2) {
    ulonglong2* p = (ulonglong2*)(buf + lane * ROWP);
#pragma unroll
    for (int q = 0; q < 8; q++) {
        ulonglong2 v;
        v.x = M2[2 * q];
        v.y = M2[2 * q + 1];
        p[q] = v;
    }
}

__device__ __forceinline__ void store_row_mn2(float* buf, int lane, const u64* M2,
                                              u64 u2, const float* k) {
    const u64* k2 = (const u64*)k;
    ulonglong2* p = (ulonglong2*)(buf + lane * ROWP);
#pragma unroll
    for (int q = 0; q < 8; q++) {
        ulonglong2 v;
        v.x = fma2_(u2, k2[2 * q],     M2[2 * q]);
        v.y = fma2_(u2, k2[2 * q + 1], M2[2 * q + 1]);
        p[q] = v;
    }
}

__device__ __forceinline__ int resolve_single(const u64* M2, u64 u2, const float* k,
                                              float& eo, bool& valid,
                                              float* mnbuf, float* mobuf,
                                              int lane, unsigned FULL)
{
    int g;
    if (valid) {
        store_row_mn2(mnbuf, lane, M2, u2, k);
        __syncwarp();
        float a = 0.0f;
        if (lane < 16) a = chain64p(mnbuf, lane);
        __syncwarp();
        float en = fold16(a, 0, FULL);
        g = en > eo;
        if (g) eo = en;
    } else {
        store_row2(mobuf, lane, M2);
        store_row_mn2(mnbuf, lane, M2, u2, k);
        __syncwarp();
        float a = chain64p((lane < 16) ? mobuf : mnbuf, lane & 15);
        __syncwarp();
        float eoc = fold16(a, 0, FULL);
        float en  = fold16(a, 16, FULL);
        g = en > eoc;
        eo = g ? en : eoc;
        valid = true;
    }
    return g;
}

// ---------------------------------------------------------------------------
__global__ void __launch_bounds__(32) scan_kernel(const int* __restrict__ seq,
                                                  const float* __restrict__ w_read,
                                                  const float* __restrict__ b_read,
                                                  const float* __restrict__ w_out,
                                                  const float* __restrict__ b_out,
                                                  float* __restrict__ out)
{
    __shared__ __align__(16) float tsh[V_ * H_];
    __shared__ __align__(16) float slowbuf[SLOWBUF_WORDS];
    __shared__ float dnsh[V_];
    __shared__ float kssh[V_];
    __shared__ int   toksA[32];
    __shared__ int   toksB[32];
    __shared__ float scratch[H_];

    const int lane = threadIdx.x;
    const int bA   = blockIdx.x;
    const int bB   = blockIdx.x + 256;
    const unsigned FULL = 0xffffffffu;
    float* mnA = slowbuf + OFF_MNA;
    float* mnB = slowbuf + OFF_MNB;
    float* moA = slowbuf + OFF_MOA;
    float* moB = slowbuf + OFF_MOB;

    for (int i = lane; i < V_ * H_; i += 32) tsh[i] = g_table[i];
    dnsh[lane]      = g_denom[lane];
    dnsh[lane + 32] = g_denom[lane + 32];
    kssh[lane]      = g_ksq[lane];
    kssh[lane + 32] = g_ksq[lane + 32];
    __syncwarp();

    u64 M2A[16], M2B[16];
#pragma unroll
    for (int j = 0; j < 16; j++) { M2A[j] = 0ULL; M2B[j] = 0ULL; }

    float eoA = 0.0f, eoB = 0.0f;
    bool validA = true, validB = true;

    int writes = 0;
    const int* sA = seq + bA * L_;
    const int* sB = seq + bB * L_;

    for (int t0 = 0; t0 < STEPS; t0 += 32) {
        toksA[lane] = sA[t0 + lane];
        toksB[lane] = sB[t0 + lane];
        __syncwarp();
        const int tend = (STEPS - t0) < 32 ? (STEPS - t0) : 32;

        for (int tt = 0; tt < tend; tt++) {
            const float* kA = tsh + toksA[tt] * H_;
            const float* kB = tsh + toksB[tt] * H_;
            const float dnA = dnsh[toksA[tt]], ksA = kssh[toksA[tt]];
            const float dnB = dnsh[toksB[tt]], ksB = kssh[toksB[tt]];

            const float vA = dot2p(M2A, kA);
            const float vB = dot2p(M2B, kB);

            const float uA = __fsub_rn(kA[lane], __fdiv_rn(vA, dnA));
            const float uB = __fsub_rn(kB[lane], __fdiv_rn(vB, dnB));

            // fast-gate dE via fixed-point s32 redux (1 instr per reduction)
            const float dEA = dE_fast(uA, vA, ksA, FULL);
            const float dEB = dE_fast(uB, vB, ksB, FULL);

            const bool slowA = fabsf(dEA) < THRESH;
            const bool slowB = fabsf(dEB) < THRESH;
            int gateA = dEA > 0.0f;
            int gateB = dEB > 0.0f;

            const u64 u2A = pk2(uA, uA);
            const u64 u2B = pk2(uB, uB);

            if (slowA | slowB) {
                if (slowA & slowB & validA & validB) {
                    store_row_mn2(mnA, lane, M2A, u2A, kA);
                    store_row_mn2(mnB, lane, M2B, u2B, kB);
                    __syncwarp();
                    float a = chain64p((lane < 16) ? mnA : mnB, lane & 15);
                    __syncwarp();
                    float enA = fold16(a, 0, FULL);
                    float enB = fold16(a, 16, FULL);
                    gateA = enA > eoA;
                    gateB = enB > eoB;
                    if (gateA) eoA = enA;
                    if (gateB) eoB = enB;
                } else {
                    if (slowA)
                        gateA = resolve_single(M2A, u2A, kA, eoA, validA, mnA, moA, lane, FULL);
                    if (slowB)
                        gateB = resolve_single(M2B, u2B, kB, eoB, validB, mnB, moB, lane, FULL);
                }
            }

            if (gateA) {
                writes++;
                const u64* k2 = (const u64*)kA;
#pragma unroll
                for (int j = 0; j < 16; j++) M2A[j] = fma2_(u2A, k2[j], M2A[j]);
                if (!slowA) validA = false;
            }
            if (gateB) {
                writes++;
                const u64* k2 = (const u64*)kB;
#pragma unroll
                for (int j = 0; j < 16; j++) M2B[j] = fma2_(u2B, k2[j], M2B[j]);
                if (!slowB) validB = false;
            }
        }
        __syncwarp();
    }

    // -------- readout (both batches), identical arithmetic --------
#pragma unroll
    for (int pass = 0; pass < 2; pass++) {
        const int b = pass ? bB : bA;
        const u64* M2 = pass ? M2B : M2A;
        const int qtok = (pass ? sB : sA)[L_ - 1];
        const float* qv = tsh + qtok * H_;
        float ctx = dot2p(M2, qv);

        scratch[lane] = ctx;
        __syncwarp();
        float r = 0.0f;
#pragma unroll
        for (int j = 0; j < H_; j++) r = fmaf(scratch[j], w_read[j * H_ + lane], r);
        r = __fadd_rn(r, b_read[lane]);
        __syncwarp();
        scratch[lane] = r;
        __syncwarp();

        float o0 = 0.0f, o1 = 0.0f;
#pragma unroll
        for (int j = 0; j < H_; j++) {
            const float rj = scratch[j];
            o0 = fmaf(rj, w_out[j * V_ + lane], o0);
            o1 = fmaf(rj, w_out[j * V_ + lane + H_], o1);
        }
        out[b * V_ + lane]      = __fadd_rn(o0, b_out[lane]);
        out[b * V_ + lane + H_] = __fadd_rn(o1, b_out[lane + H_]);
        __syncwarp();
    }

    if (lane == 0) atomicAdd(&g_writes, writes);
}

// ---------------------------------------------------------------------------
__global__ void finalize_kernel(float* __restrict__ out, int out_size)
{
    if (out_size > B_ * V_)
        out[B_ * V_] = __fdiv_rn((float)g_writes, (float)(STEPS * B_));
}

extern "C" void kernel_launch(void* const* d_in, const int* in_sizes, int n_in,
                              void* d_out, int out_size)
{
    const int*   seq    = (const int*)d_in[0];
    const float* embed  = (const float*)d_in[1];
    const float* w1     = (const float*)d_in[2];
    const float* b1     = (const float*)d_in[3];
    const float* w2     = (const float*)d_in[4];
    const float* b2     = (const float*)d_in[5];
    const float* ln_g   = (const float*)d_in[6];
    const float* ln_b   = (const float*)d_in[7];
    const float* w_read = (const float*)d_in[8];
    const float* b_read = (const float*)d_in[9];
    const float* w_out  = (const float*)d_in[10];
    const float* b_out  = (const float*)d_in[11];
    float* out = (float*)d_out;

    precompute_kernel<<<V_, 64>>>(embed, w1, b1, w2, b2, ln_g, ln_b);
    scan_kernel<<<B_ / 2, 32>>>(seq, w_read, b_read, w_out, b_out, out);
    finalize_kernel<<<1, 1>>>(out, out_size);
}